// round 16
// baseline (speedup 1.0000x reference)
#include <cuda_runtime.h>
#include <cuda_bf16.h>
#include <cstdint>

#define M_NODES 50000
#define N_EDGES 600000
#define IN_DIM  256
#define H_DIM   128
#define MH ((size_t)M_NODES * H_DIM)

#define SCAN_TILE 4096
#define SCAN_NBLK ((M_NODES + SCAN_TILE - 1) / SCAN_TILE)   // 13

// ---------------------------------------------------------------------------
// Device scratch
//  g_V layout: [3 rel][3 combo][MH]  (V0 = h*C0, V1 = h*C1, V2 = h*C2)
//  g_P: [3 rel][MH] intermediate P_r = V1_r - Ahat_r V2_r
// ---------------------------------------------------------------------------
__device__ __align__(256) float g_V[9 * MH];
__device__ __align__(256) float g_P[3 * MH];
__device__ __align__(256) float g_dinv3[3 * M_NODES];
__device__ __align__(256) int   g_cnt[3 * M_NODES];
__device__ __align__(256) int   g_cur[3 * M_NODES];
__device__ __align__(256) int   g_blk[3 * SCAN_NBLK];
__device__ __align__(256) int   g_sorted[(size_t)3 * N_EDGES];

__device__ __align__(256) __nv_bfloat16 g_Bt1h[3 * 128 * 256];
__device__ __align__(256) __nv_bfloat16 g_Bt1l[3 * 128 * 256];
__device__ __align__(256) __nv_bfloat16 g_Bt2h[3 * 128 * 128];
__device__ __align__(256) __nv_bfloat16 g_Bt2l[3 * 128 * 128];
__device__ __align__(256) __nv_bfloat16 g_Bt3h[3 * 128 * 128];   // combos C0,C1,C2 [n][k]
__device__ __align__(256) __nv_bfloat16 g_Bt3l[3 * 128 * 128];

__device__ __forceinline__ float leaky(float v) { return v > 0.0f ? v : 0.01f * v; }

__device__ __forceinline__ uint32_t s2u(const void* p) {
    uint32_t a;
    asm("{ .reg .u64 t; cvta.to.shared.u64 t, %1; cvt.u32.u64 %0, t; }" : "=r"(a) : "l"(p));
    return a;
}
__device__ __forceinline__ void ldm_x4(uint32_t* r, uint32_t addr) {
    asm volatile("ldmatrix.sync.aligned.m8n8.x4.shared.b16 {%0,%1,%2,%3}, [%4];"
                 : "=r"(r[0]), "=r"(r[1]), "=r"(r[2]), "=r"(r[3]) : "r"(addr));
}
__device__ __forceinline__ void mma16816(float* c, const uint32_t* a, const uint32_t* b) {
    asm volatile(
        "mma.sync.aligned.m16n8k16.row.col.f32.bf16.bf16.f32 "
        "{%0,%1,%2,%3}, {%4,%5,%6,%7}, {%8,%9}, {%0,%1,%2,%3};"
        : "+f"(c[0]), "+f"(c[1]), "+f"(c[2]), "+f"(c[3])
        : "r"(a[0]), "r"(a[1]), "r"(a[2]), "r"(a[3]), "r"(b[0]), "r"(b[1]));
}
__device__ __forceinline__ void split2(float x, float y, uint32_t& hi, uint32_t& lo) {
    __nv_bfloat162 h;
    h.x = __float2bfloat16(x);
    h.y = __float2bfloat16(y);
    __nv_bfloat162 l;
    l.x = __float2bfloat16(x - __bfloat162float(h.x));
    l.y = __float2bfloat16(y - __bfloat162float(h.y));
    hi = *(uint32_t*)&h;
    lo = *(uint32_t*)&l;
}
__device__ __forceinline__ void cpa16(uint32_t d, const void* s) {
    asm volatile("cp.async.cg.shared.global [%0], [%1], 16;" :: "r"(d), "l"(s) : "memory");
}
#define CPA_COMMIT() asm volatile("cp.async.commit_group;" ::: "memory")
#define CPA_WAIT1()  asm volatile("cp.async.wait_group 1;" ::: "memory")
#define CPA_WAIT0()  asm volatile("cp.async.wait_group 0;" ::: "memory")

#define SPAD 40
#define H1S  136
#define BSTEP (128 * SPAD)   // halves per operand buffer

// smem layout (halves): A hi/lo, B buf0 hi/lo, B buf1 hi/lo, H1 hi/lo
#define O_AH  0
#define O_AL  (1 * BSTEP)
#define O_B0H (2 * BSTEP)
#define O_B0L (3 * BSTEP)
#define O_B1H (4 * BSTEP)
#define O_B1L (5 * BSTEP)
#define O_H1H (6 * BSTEP)
#define O_H1L (O_H1H + 128 * H1S)
#define SMEM_F12_BYTES ((O_H1L + 128 * H1S) * 2)

// Prefetch one 128x32-half B tile pair (hi+lo) into buffer `bh_byte`
// (lo at +BSTEP*2 bytes). BST = global row stride in halves.
template <int BST>
__device__ __forceinline__ void prefB(uint32_t bh_byte, const __nv_bfloat16* Bh,
                                      const __nv_bfloat16* Bl, int k0, int tid) {
#pragma unroll
    for (int it = 0; it < 2; it++) {
        int i = it * 256 + tid;
        int r = i >> 2, seg = i & 3;
        uint32_t d = bh_byte + (uint32_t)(r * SPAD + seg * 8) * 2;
        const size_t go = (size_t)r * BST + k0 + seg * 8;
        cpa16(d, Bh + go);
        cpa16(d + BSTEP * 2, Bl + go);
    }
}

// ---------------------------------------------------------------------------
// Fused MLP + output projections (pipelined B loads):
//   A: acc = x @ W1^T (K=256);  h1 = leaky(acc+b1) -> smem
//   C: acc = h1 @ W2^T (K=128); T0 = leaky(acc+b2) -> smem (overwrites h1)
//   Vj: g_V[rel][j] = T0 @ C_j^T (K=128)
// ---------------------------------------------------------------------------
__global__ void __launch_bounds__(256, 1)
fused12v_kernel(const float* __restrict__ x,
                const float* __restrict__ b1_0, const float* __restrict__ b1_1,
                const float* __restrict__ b1_2,
                const float* __restrict__ b2_0, const float* __restrict__ b2_1,
                const float* __restrict__ b2_2) {
    extern __shared__ __nv_bfloat16 sm[];
    const int tid = threadIdx.x;
    const int wid = tid >> 5;
    const int lane = tid & 31;
    const int row0 = blockIdx.x * 128;
    const int rel = blockIdx.y;
    const int wm0 = (wid & 1) * 64;
    const int wn0 = (wid >> 1) * 32;

    const float* b1 = rel == 0 ? b1_0 : (rel == 1 ? b1_1 : b1_2);
    const float* b2 = rel == 0 ? b2_0 : (rel == 1 ? b2_1 : b2_2);

    const uint32_t base = s2u(sm);
    const uint32_t uAh = base + O_AH * 2, uAl = base + O_AL * 2;
    const uint32_t uH1h = base + O_H1H * 2, uH1l = base + O_H1L * 2;
    const uint32_t bufH[2] = {base + O_B0H * 2, base + O_B1H * 2};

    const int a_row = (lane & 7) + ((lane >> 3) & 1) * 8;
    const int a_kof = ((lane >> 4) & 1) * 8;
    const int b_nof = ((lane >> 4) & 1) * 8;
    const int b_kof = ((lane >> 3) & 1) * 8;
    const int b_row = lane & 7;
    const int lr = lane >> 2;
    const int lc = (lane & 3) * 2;

    float acc[4][4][4] = {};

    // ---------------- Phase A: x @ W1^T (K=256) ----------------
    const __nv_bfloat16* B1h = g_Bt1h + rel * 128 * 256;
    const __nv_bfloat16* B1l = g_Bt1l + rel * 128 * 256;

    prefB<256>(bufH[0], B1h, B1l, 0, tid);
    CPA_COMMIT();
    int buf = 0;
    for (int k0 = 0; k0 < 256; k0 += 32) {
        __syncthreads();                               // prior compute done
        const bool more = (k0 + 32 < 256);
        if (more) { prefB<256>(bufH[buf ^ 1], B1h, B1l, k0 + 32, tid); CPA_COMMIT(); }
        // A load + split (synchronous; overlaps outstanding B copy)
#pragma unroll
        for (int it = 0; it < 2; it++) {
            int i = it * 256 + tid;
            int r = i >> 2, q = (i & 3) * 8;
            int gr = row0 + r;
            float4 f0 = make_float4(0.f, 0.f, 0.f, 0.f);
            float4 f1 = make_float4(0.f, 0.f, 0.f, 0.f);
            if (gr < M_NODES) {
                const float* ap = x + (size_t)gr * 256 + k0 + q;
                f0 = *(const float4*)ap;
                f1 = *(const float4*)(ap + 4);
            }
            uint4 H, L;
            split2(f0.x, f0.y, H.x, L.x);
            split2(f0.z, f0.w, H.y, L.y);
            split2(f1.x, f1.y, H.z, L.z);
            split2(f1.z, f1.w, H.w, L.w);
            *(uint4*)(sm + O_AH + r * SPAD + q) = H;
            *(uint4*)(sm + O_AL + r * SPAD + q) = L;
        }
        if (more) { CPA_WAIT1(); } else { CPA_WAIT0(); }
        __syncthreads();
        const uint32_t uBh = bufH[buf], uBl = bufH[buf] + BSTEP * 2;
#pragma unroll
        for (int ks = 0; ks < 32; ks += 16) {
            uint32_t ah[4][4], al[4][4], bh[4][2], bl[4][2];
#pragma unroll
            for (int mf = 0; mf < 4; mf++) {
                uint32_t off = ((wm0 + mf * 16 + a_row) * SPAD + ks + a_kof) * 2;
                ldm_x4(ah[mf], uAh + off);
                ldm_x4(al[mf], uAl + off);
            }
#pragma unroll
            for (int nb = 0; nb < 2; nb++) {
                uint32_t off = ((wn0 + nb * 16 + b_nof + b_row) * SPAD + ks + b_kof) * 2;
                uint32_t t[4];
                ldm_x4(t, uBh + off);
                bh[2 * nb][0] = t[0]; bh[2 * nb][1] = t[1];
                bh[2 * nb + 1][0] = t[2]; bh[2 * nb + 1][1] = t[3];
                ldm_x4(t, uBl + off);
                bl[2 * nb][0] = t[0]; bl[2 * nb][1] = t[1];
                bl[2 * nb + 1][0] = t[2]; bl[2 * nb + 1][1] = t[3];
            }
#pragma unroll
            for (int mf = 0; mf < 4; mf++)
#pragma unroll
                for (int nf = 0; nf < 4; nf++) {
                    mma16816(acc[mf][nf], ah[mf], bh[nf]);
                    mma16816(acc[mf][nf], ah[mf], bl[nf]);
                    mma16816(acc[mf][nf], al[mf], bh[nf]);
                }
        }
        buf ^= 1;
    }

    // h1 -> resident smem (prefetch phase-C chunk 0 first, overlaps epilogue)
    __syncthreads();
    const __nv_bfloat16* B2h = g_Bt2h + rel * 128 * 128;
    const __nv_bfloat16* B2l = g_Bt2l + rel * 128 * 128;
    prefB<128>(bufH[0], B2h, B2l, 0, tid);
    CPA_COMMIT();
#pragma unroll
    for (int mf = 0; mf < 4; mf++)
#pragma unroll
        for (int half = 0; half < 2; half++) {
            int row = wm0 + mf * 16 + lr + half * 8;
#pragma unroll
            for (int nf = 0; nf < 4; nf++) {
                int col = wn0 + nf * 8 + lc;
                float v0 = leaky(acc[mf][nf][2 * half]     + __ldg(b1 + col));
                float v1 = leaky(acc[mf][nf][2 * half + 1] + __ldg(b1 + col + 1));
                uint32_t hi, lo;
                split2(v0, v1, hi, lo);
                *(uint32_t*)(sm + O_H1H + row * H1S + col) = hi;
                *(uint32_t*)(sm + O_H1L + row * H1S + col) = lo;
            }
        }
#pragma unroll
    for (int mf = 0; mf < 4; mf++)
#pragma unroll
        for (int nf = 0; nf < 4; nf++)
#pragma unroll
            for (int q = 0; q < 4; q++) acc[mf][nf][q] = 0.f;

    // ---------------- Phase C: h1 @ W2^T (K=128) ----------------
    buf = 0;
    for (int k0 = 0; k0 < 128; k0 += 32) {
        __syncthreads();                               // h1 visible / prior compute done
        const bool more = (k0 + 32 < 128);
        if (more) { prefB<128>(bufH[buf ^ 1], B2h, B2l, k0 + 32, tid); CPA_COMMIT(); }
        if (more) { CPA_WAIT1(); } else { CPA_WAIT0(); }
        __syncthreads();
        const uint32_t uBh = bufH[buf], uBl = bufH[buf] + BSTEP * 2;
#pragma unroll
        for (int ks = 0; ks < 32; ks += 16) {
            uint32_t ah[4][4], al[4][4], bh[4][2], bl[4][2];
#pragma unroll
            for (int mf = 0; mf < 4; mf++) {
                uint32_t off = ((wm0 + mf * 16 + a_row) * H1S + k0 + ks + a_kof) * 2;
                ldm_x4(ah[mf], uH1h + off);
                ldm_x4(al[mf], uH1l + off);
            }
#pragma unroll
            for (int nb = 0; nb < 2; nb++) {
                uint32_t off = ((wn0 + nb * 16 + b_nof + b_row) * SPAD + ks + b_kof) * 2;
                uint32_t t[4];
                ldm_x4(t, uBh + off);
                bh[2 * nb][0] = t[0]; bh[2 * nb][1] = t[1];
                bh[2 * nb + 1][0] = t[2]; bh[2 * nb + 1][1] = t[3];
                ldm_x4(t, uBl + off);
                bl[2 * nb][0] = t[0]; bl[2 * nb][1] = t[1];
                bl[2 * nb + 1][0] = t[2]; bl[2 * nb + 1][1] = t[3];
            }
#pragma unroll
            for (int mf = 0; mf < 4; mf++)
#pragma unroll
                for (int nf = 0; nf < 4; nf++) {
                    mma16816(acc[mf][nf], ah[mf], bh[nf]);
                    mma16816(acc[mf][nf], ah[mf], bl[nf]);
                    mma16816(acc[mf][nf], al[mf], bh[nf]);
                }
        }
        buf ^= 1;
    }

    // T0 = leaky(acc+b2) -> resident smem (overwrite h1)
    __syncthreads();   // all phase-C reads of H1 done
#pragma unroll
    for (int mf = 0; mf < 4; mf++)
#pragma unroll
        for (int half = 0; half < 2; half++) {
            int row = wm0 + mf * 16 + lr + half * 8;
#pragma unroll
            for (int nf = 0; nf < 4; nf++) {
                int col = wn0 + nf * 8 + lc;
                float v0 = leaky(acc[mf][nf][2 * half]     + __ldg(b2 + col));
                float v1 = leaky(acc[mf][nf][2 * half + 1] + __ldg(b2 + col + 1));
                uint32_t hi, lo;
                split2(v0, v1, hi, lo);
                *(uint32_t*)(sm + O_H1H + row * H1S + col) = hi;
                *(uint32_t*)(sm + O_H1L + row * H1S + col) = lo;
            }
        }

    // ---------------- V phases: g_V[rel][j] = T0 @ C_j^T (K=128) -------------
#pragma unroll 1
    for (int j = 0; j < 3; j++) {
#pragma unroll
        for (int mf = 0; mf < 4; mf++)
#pragma unroll
            for (int nf = 0; nf < 4; nf++)
#pragma unroll
                for (int q = 0; q < 4; q++) acc[mf][nf][q] = 0.f;

        const __nv_bfloat16* Bjh = g_Bt3h + j * 128 * 128;
        const __nv_bfloat16* Bjl = g_Bt3l + j * 128 * 128;
        prefB<128>(bufH[0], Bjh, Bjl, 0, tid);
        CPA_COMMIT();
        buf = 0;
        for (int k0 = 0; k0 < 128; k0 += 32) {
            __syncthreads();                           // T0 visible / prior compute done
            const bool more = (k0 + 32 < 128);
            if (more) { prefB<128>(bufH[buf ^ 1], Bjh, Bjl, k0 + 32, tid); CPA_COMMIT(); }
            if (more) { CPA_WAIT1(); } else { CPA_WAIT0(); }
            __syncthreads();
            const uint32_t uBh = bufH[buf], uBl = bufH[buf] + BSTEP * 2;
#pragma unroll
            for (int ks = 0; ks < 32; ks += 16) {
                uint32_t ah[4][4], al[4][4], bh[4][2], bl[4][2];
#pragma unroll
                for (int mf = 0; mf < 4; mf++) {
                    uint32_t off = ((wm0 + mf * 16 + a_row) * H1S + k0 + ks + a_kof) * 2;
                    ldm_x4(ah[mf], uH1h + off);
                    ldm_x4(al[mf], uH1l + off);
                }
#pragma unroll
                for (int nb = 0; nb < 2; nb++) {
                    uint32_t off = ((wn0 + nb * 16 + b_nof + b_row) * SPAD + ks + b_kof) * 2;
                    uint32_t t[4];
                    ldm_x4(t, uBh + off);
                    bh[2 * nb][0] = t[0]; bh[2 * nb][1] = t[1];
                    bh[2 * nb + 1][0] = t[2]; bh[2 * nb + 1][1] = t[3];
                    ldm_x4(t, uBl + off);
                    bl[2 * nb][0] = t[0]; bl[2 * nb][1] = t[1];
                    bl[2 * nb + 1][0] = t[2]; bl[2 * nb + 1][1] = t[3];
                }
#pragma unroll
                for (int mf = 0; mf < 4; mf++)
#pragma unroll
                    for (int nf = 0; nf < 4; nf++) {
                        mma16816(acc[mf][nf], ah[mf], bh[nf]);
                        mma16816(acc[mf][nf], ah[mf], bl[nf]);
                        mma16816(acc[mf][nf], al[mf], bh[nf]);
                    }
            }
            buf ^= 1;
        }

        float* Vj = g_V + (size_t)(rel * 3 + j) * MH;
#pragma unroll
        for (int mf = 0; mf < 4; mf++)
#pragma unroll
            for (int half = 0; half < 2; half++) {
                int row = row0 + wm0 + mf * 16 + lr + half * 8;
                if (row >= M_NODES) continue;
#pragma unroll
                for (int nf = 0; nf < 4; nf++) {
                    int col = wn0 + nf * 8 + lc;
                    *(float2*)(Vj + (size_t)row * H_DIM + col) =
                        make_float2(acc[mf][nf][2 * half], acc[mf][nf][2 * half + 1]);
                }
            }
    }
}

// ---------------------------------------------------------------------------
// Weight prep: W1/W2 split; W3 -> combos C0=e0+e1+e2, C1=e1+2e2, C2=e2
// ---------------------------------------------------------------------------
#define W1_TOT (3 * 128 * 256)
#define W2_TOT (3 * 128 * 128)
#define W3_TOT (128 * 128)

__global__ void convW_all(const float* __restrict__ W1a, const float* __restrict__ W1b,
                          const float* __restrict__ W1c, const float* __restrict__ W2a,
                          const float* __restrict__ W2b, const float* __restrict__ W2c,
                          const float* __restrict__ W3) {
    int i = blockIdx.x * blockDim.x + threadIdx.x;
    if (i < W1_TOT) {
        int r = i / 32768, rem = i % 32768, n = rem >> 8, k = rem & 255;
        const float* W = r == 0 ? W1a : (r == 1 ? W1b : W1c);
        float v = W[k * H_DIM + n];
        __nv_bfloat16 h = __float2bfloat16(v);
        g_Bt1h[i] = h;
        g_Bt1l[i] = __float2bfloat16(v - __bfloat162float(h));
        return;
    }
    i -= W1_TOT;
    if (i < W2_TOT) {
        int r = i >> 14, rem = i & 16383, n = rem >> 7, k = rem & 127;
        const float* W = r == 0 ? W2a : (r == 1 ? W2b : W2c);
        float v = W[k * H_DIM + n];
        __nv_bfloat16 h = __float2bfloat16(v);
        g_Bt2h[i] = h;
        g_Bt2l[i] = __float2bfloat16(v - __bfloat162float(h));
        return;
    }
    i -= W2_TOT;
    if (i < W3_TOT) {
        int n = i >> 7, k = i & 127;
        float w0 = W3[(0 * 128 + k) * 128 + n];
        float w1 = W3[(1 * 128 + k) * 128 + n];
        float w2 = W3[(2 * 128 + k) * 128 + n];
        float e0 = 3.0f * w0;
        float e1 = -3.0f * w0 + 3.0f * w1;
        float e2 = 0.75f * w0 - 1.5f * w1 + 0.75f * w2;
        float c[3];
        c[0] = e0 + e1 + e2;
        c[1] = e1 + 2.0f * e2;
        c[2] = e2;
#pragma unroll
        for (int s = 0; s < 3; s++) {
            __nv_bfloat16 h = __float2bfloat16(c[s]);
            g_Bt3h[s * 128 * 128 + n * 128 + k] = h;
            g_Bt3l[s * 128 * 128 + n * 128 + k] = __float2bfloat16(c[s] - __bfloat162float(h));
        }
    }
}

// ---------------------------------------------------------------------------
// Graph preprocessing
// ---------------------------------------------------------------------------
__global__ void zero_cnt_kernel() {
    int i = blockIdx.x * blockDim.x + threadIdx.x;
    if (i < 3 * M_NODES) g_cnt[i] = 0;
}
__global__ void deg3_kernel(const int* __restrict__ d0, const int* __restrict__ d1,
                            const int* __restrict__ d2) {
    int t = blockIdx.x * blockDim.x + threadIdx.x;
    if (t >= 3 * N_EDGES) return;
    int r = t / N_EDGES, e = t - r * N_EDGES;
    const int* d = r == 0 ? d0 : (r == 1 ? d1 : d2);
    atomicAdd(&g_cnt[r * M_NODES + __ldg(d + e)], 1);
}

__global__ void scanA_kernel() {
    __shared__ int wsum[8];
    const int r = blockIdx.y, b = blockIdx.x;
    const int tid = threadIdx.x;
    const int base = b * SCAN_TILE + tid * 16;

    int s = 0;
#pragma unroll
    for (int k = 0; k < 16; k++) {
        int i = base + k;
        if (i < M_NODES) {
            int v = g_cnt[r * M_NODES + i];
            g_dinv3[r * M_NODES + i] = rsqrtf(fmaxf((float)v, 1.0f));
            s += v;
        }
    }
#pragma unroll
    for (int o = 16; o > 0; o >>= 1) s += __shfl_down_sync(0xFFFFFFFFu, s, o);
    if ((tid & 31) == 0) wsum[tid >> 5] = s;
    __syncthreads();
    if (tid == 0) {
        int t = 0;
#pragma unroll
        for (int w = 0; w < 8; w++) t += wsum[w];
        g_blk[r * SCAN_NBLK + b] = t;
    }
}

__global__ void scanB_kernel() {
    int r = threadIdx.x;
    if (r >= 3) return;
    int run = 0;
#pragma unroll
    for (int b = 0; b < SCAN_NBLK; b++) {
        int t = g_blk[r * SCAN_NBLK + b];
        g_blk[r * SCAN_NBLK + b] = run;
        run += t;
    }
}

__global__ void scanC_kernel() {
    __shared__ int warp_sums[8];
    const int r = blockIdx.y, b = blockIdx.x;
    const int tid = threadIdx.x;
    const int lane = tid & 31;
    const int wid = tid >> 5;
    const int base = b * SCAN_TILE + tid * 16;

    int v[16];
    int tsum = 0;
#pragma unroll
    for (int k = 0; k < 16; k++) {
        int i = base + k;
        v[k] = (i < M_NODES) ? g_cnt[r * M_NODES + i] : 0;
        tsum += v[k];
    }
    int x = tsum;
#pragma unroll
    for (int o = 1; o < 32; o <<= 1) {
        int y = __shfl_up_sync(0xFFFFFFFFu, x, o);
        if (lane >= o) x += y;
    }
    if (lane == 31) warp_sums[wid] = x;
    __syncthreads();
    if (wid == 0 && lane < 8) {
        int w = warp_sums[lane];
#pragma unroll
        for (int o = 1; o < 8; o <<= 1) {
            int y = __shfl_up_sync(0xFFu, w, o);
            if (lane >= o) w += y;
        }
        warp_sums[lane] = w;
    }
    __syncthreads();
    int woff = (wid > 0) ? warp_sums[wid - 1] : 0;
    int run = g_blk[r * SCAN_NBLK + b] + woff + x - tsum;
#pragma unroll
    for (int k = 0; k < 16; k++) {
        int i = base + k;
        if (i < M_NODES) g_cur[r * M_NODES + i] = run;
        run += v[k];
    }
}

__global__ void fill_kernel(const int* __restrict__ s0, const int* __restrict__ s1,
                            const int* __restrict__ s2, const int* __restrict__ d0,
                            const int* __restrict__ d1, const int* __restrict__ d2) {
    int t = blockIdx.x * blockDim.x + threadIdx.x;
    if (t >= 3 * N_EDGES) return;
    int r = t / N_EDGES, e = t - r * N_EDGES;
    const int* sp = r == 0 ? s0 : (r == 1 ? s1 : s2);
    const int* dp = r == 0 ? d0 : (r == 1 ? d1 : d2);
    int s = __ldg(sp + e);
    int d = __ldg(dp + e);
    int p = atomicAdd(&g_cur[r * M_NODES + d], 1);
    g_sorted[(size_t)r * N_EDGES + p] = s;
}

// ---------------------------------------------------------------------------
// Step 1: P_r[n] = V1_r[n] - dinv[n] * sum_seg dinv[src] * V2_r[src]
// one warp per (rel, node); 4-edge unrolled gather
// ---------------------------------------------------------------------------
__global__ void __launch_bounds__(256) prop1_kernel() {
    int t = blockIdx.x * blockDim.x + threadIdx.x;
    int w = t >> 5;
    if (w >= 3 * M_NODES) return;
    const int lane = t & 31;
    const int r = w / M_NODES, n = w - r * M_NODES;
    const int rn = r * M_NODES + n;
    const int end = __ldg(&g_cur[rn]);
    const int cnt = __ldg(&g_cnt[rn]);
    int j = end - cnt;
    const int* ss = g_sorted + (size_t)r * N_EDGES;
    const float* V2 = g_V + (size_t)(r * 3 + 2) * MH;
    const float* dv = g_dinv3 + r * M_NODES;

    float4 a0 = make_float4(0.f, 0.f, 0.f, 0.f);
    float4 a1 = make_float4(0.f, 0.f, 0.f, 0.f);
    for (; j + 4 <= end; j += 4) {
        int s0 = __ldg(ss + j);
        int s1 = __ldg(ss + j + 1);
        int s2 = __ldg(ss + j + 2);
        int s3 = __ldg(ss + j + 3);
        float e0 = __ldg(dv + s0);
        float e1 = __ldg(dv + s1);
        float e2 = __ldg(dv + s2);
        float e3 = __ldg(dv + s3);
        float4 v0 = *(const float4*)(V2 + (size_t)s0 * H_DIM + lane * 4);
        float4 v1 = *(const float4*)(V2 + (size_t)s1 * H_DIM + lane * 4);
        float4 v2 = *(const float4*)(V2 + (size_t)s2 * H_DIM + lane * 4);
        float4 v3 = *(const float4*)(V2 + (size_t)s3 * H_DIM + lane * 4);
        a0.x += v0.x * e0; a0.y += v0.y * e0; a0.z += v0.z * e0; a0.w += v0.w * e0;
        a1.x += v1.x * e1; a1.y += v1.y * e1; a1.z += v1.z * e1; a1.w += v1.w * e1;
        a0.x += v2.x * e2; a0.y += v2.y * e2; a0.z += v2.z * e2; a0.w += v2.w * e2;
        a1.x += v3.x * e3; a1.y += v3.y * e3; a1.z += v3.z * e3; a1.w += v3.w * e3;
    }
    for (; j < end; j++) {
        int s0 = __ldg(ss + j);
        float e0 = __ldg(dv + s0);
        float4 v0 = *(const float4*)(V2 + (size_t)s0 * H_DIM + lane * 4);
        a0.x += v0.x * e0; a0.y += v0.y * e0; a0.z += v0.z * e0; a0.w += v0.w * e0;
    }
    float dn = __ldg(dv + n);
    float4 b = *(const float4*)(g_V + (size_t)(r * 3 + 1) * MH + (size_t)n * H_DIM + lane * 4);
    float4 o;
    o.x = b.x - (a0.x + a1.x) * dn;
    o.y = b.y - (a0.y + a1.y) * dn;
    o.z = b.z - (a0.z + a1.z) * dn;
    o.w = b.w - (a0.w + a1.w) * dn;
    *(float4*)(g_P + (size_t)r * MH + (size_t)n * H_DIM + lane * 4) = o;
}

// ---------------------------------------------------------------------------
// Step 2: out[n] = leaky( b3 + sum_r [ V0_r[n] - dinv_r[n]*sum_seg dinv_r[s]*P_r[s] ] )
// one warp per node; 4-edge unrolled gather
// ---------------------------------------------------------------------------
__global__ void __launch_bounds__(256) prop2_kernel(const float* __restrict__ b3,
                                                    float* __restrict__ out) {
    int t = blockIdx.x * blockDim.x + threadIdx.x;
    int n = t >> 5;
    if (n >= M_NODES) return;
    const int lane = t & 31;

    float4 acc = *(const float4*)(b3 + lane * 4);

#pragma unroll 1
    for (int r = 0; r < 3; r++) {
        const int rn = r * M_NODES + n;
        const int end = __ldg(&g_cur[rn]);
        const int cnt = __ldg(&g_cnt[rn]);
        int j = end - cnt;
        const int* ss = g_sorted + (size_t)r * N_EDGES;
        const float* P = g_P + (size_t)r * MH;
        const float* dv = g_dinv3 + r * M_NODES;

        float4 a0 = make_float4(0.f, 0.f, 0.f, 0.f);
        float4 a1 = make_float4(0.f, 0.f, 0.f, 0.f);
        for (; j + 4 <= end; j += 4) {
            int s0 = __ldg(ss + j);
            int s1 = __ldg(ss + j + 1);
            int s2 = __ldg(ss + j + 2);
            int s3 = __ldg(ss + j + 3);
            float e0 = __ldg(dv + s0);
            float e1 = __ldg(dv + s1);
            float e2 = __ldg(dv + s2);
            float e3 = __ldg(dv + s3);
            float4 v0 = *(const float4*)(P + (size_t)s0 * H_DIM + lane * 4);
            float4 v1 = *(const float4*)(P + (size_t)s1 * H_DIM + lane * 4);
            float4 v2 = *(const float4*)(P + (size_t)s2 * H_DIM + lane * 4);
            float4 v3 = *(const float4*)(P + (size_t)s3 * H_DIM + lane * 4);
            a0.x += v0.x * e0; a0.y += v0.y * e0; a0.z += v0.z * e0; a0.w += v0.w * e0;
            a1.x += v1.x * e1; a1.y += v1.y * e1; a1.z += v1.z * e1; a1.w += v1.w * e1;
            a0.x += v2.x * e2; a0.y += v2.y * e2; a0.z += v2.z * e2; a0.w += v2.w * e2;
            a1.x += v3.x * e3; a1.y += v3.y * e3; a1.z += v3.z * e3; a1.w += v3.w * e3;
        }
        for (; j < end; j++) {
            int s0 = __ldg(ss + j);
            float e0 = __ldg(dv + s0);
            float4 v0 = *(const float4*)(P + (size_t)s0 * H_DIM + lane * 4);
            a0.x += v0.x * e0; a0.y += v0.y * e0; a0.z += v0.z * e0; a0.w += v0.w * e0;
        }
        float dn = __ldg(dv + n);
        float4 V0 = *(const float4*)(g_V + (size_t)(r * 3) * MH + (size_t)n * H_DIM + lane * 4);
        acc.x += V0.x - (a0.x + a1.x) * dn;
        acc.y += V0.y - (a0.y + a1.y) * dn;
        acc.z += V0.z - (a0.z + a1.z) * dn;
        acc.w += V0.w - (a0.w + a1.w) * dn;
    }

    float4 o;
    o.x = leaky(acc.x); o.y = leaky(acc.y); o.z = leaky(acc.z); o.w = leaky(acc.w);
    *(float4*)(out + (size_t)n * H_DIM + lane * 4) = o;
}

// ---------------------------------------------------------------------------
// Launch
// ---------------------------------------------------------------------------
extern "C" void kernel_launch(void* const* d_in, const int* in_sizes, int n_in,
                              void* d_out, int out_size) {
    const float* x = (const float*)d_in[0];
    const int *src[3], *dst[3];
    const float *W1[3], *b1[3], *W2[3], *b2[3];
    const float *W3, *b3;

    if (in_sizes[3] == N_EDGES) {
        for (int r = 0; r < 3; r++) {
            src[r] = (const int*)d_in[1 + 2 * r];
            dst[r] = (const int*)d_in[2 + 2 * r];
        }
        for (int r = 0; r < 3; r++) {
            W1[r] = (const float*)d_in[7 + 4 * r];
            b1[r] = (const float*)d_in[8 + 4 * r];
            W2[r] = (const float*)d_in[9 + 4 * r];
            b2[r] = (const float*)d_in[10 + 4 * r];
        }
        W3 = (const float*)d_in[19];
        b3 = (const float*)d_in[20];
    } else {
        for (int r = 0; r < 3; r++) {
            src[r] = (const int*)d_in[1 + 6 * r];
            dst[r] = (const int*)d_in[2 + 6 * r];
            W1[r]  = (const float*)d_in[3 + 6 * r];
            b1[r]  = (const float*)d_in[4 + 6 * r];
            W2[r]  = (const float*)d_in[5 + 6 * r];
            b2[r]  = (const float*)d_in[6 + 6 * r];
        }
        W3 = (const float*)d_in[19];
        b3 = (const float*)d_in[20];
    }

    cudaFuncSetAttribute(fused12v_kernel, cudaFuncAttributeMaxDynamicSharedMemorySize,
                         SMEM_F12_BYTES);

    const int GEMM_X = (M_NODES + 127) / 128;                    // 391
    const int E3     = (3 * N_EDGES + 255) / 256;
    const int NV3    = (3 * M_NODES + 255) / 256;
    const int SEG3   = (int)(((size_t)3 * M_NODES * 32 + 255) / 256);
    const int SEG1   = (int)(((size_t)M_NODES * 32 + 255) / 256);
    const int CW     = (W1_TOT + W2_TOT + W3_TOT + 255) / 256;

    cudaStream_t sSide;
    cudaEvent_t evFork, evPrep;
    cudaStreamCreateWithFlags(&sSide, cudaStreamNonBlocking);
    cudaEventCreateWithFlags(&evFork, cudaEventDisableTiming);
    cudaEventCreateWithFlags(&evPrep, cudaEventDisableTiming);

    cudaEventRecord(evFork, 0);
    cudaStreamWaitEvent(sSide, evFork, 0);

    // Side chain: graph preprocessing (overlaps the GEMM work)
    zero_cnt_kernel<<<NV3, 256, 0, sSide>>>();
    deg3_kernel<<<E3, 256, 0, sSide>>>(dst[0], dst[1], dst[2]);
    {
        dim3 sg(SCAN_NBLK, 3);
        scanA_kernel<<<sg, 256, 0, sSide>>>();
        scanB_kernel<<<1, 32, 0, sSide>>>();
        scanC_kernel<<<sg, 256, 0, sSide>>>();
    }
    fill_kernel<<<E3, 256, 0, sSide>>>(src[0], src[1], src[2], dst[0], dst[1], dst[2]);
    cudaEventRecord(evPrep, sSide);

    // Main: all GEMM work (MLP + output projections V0/V1/V2)
    convW_all<<<CW, 256>>>(W1[0], W1[1], W1[2], W2[0], W2[1], W2[2], W3);
    {
        dim3 g(GEMM_X, 3);
        fused12v_kernel<<<g, 256, SMEM_F12_BYTES>>>(x, b1[0], b1[1], b1[2], b2[0], b2[1], b2[2]);
    }

    // Propagation directly produces the output
    cudaStreamWaitEvent(0, evPrep, 0);
    prop1_kernel<<<SEG3, 256>>>();
    prop2_kernel<<<SEG1, 256>>>(b3, (float*)d_out);
}

// round 17
// speedup vs baseline: 1.2748x; 1.2748x over previous
#include <cuda_runtime.h>
#include <cuda_bf16.h>
#include <cstdint>

#define M_NODES 50000
#define N_EDGES 600000
#define IN_DIM  256
#define H_DIM   128
#define MH ((size_t)M_NODES * H_DIM)

#define SCAN_TILE 4096
#define SCAN_NBLK ((M_NODES + SCAN_TILE - 1) / SCAN_TILE)   // 13

// ---------------------------------------------------------------------------
// Device scratch
//  g_V layout: [3 rel][3 combo][MH]  (V0 = h*C0, V1 = h*C1, V2 = h*C2)
//  g_P: [3 rel][MH] intermediate P_r = V1_r - Ahat_r V2_r
// ---------------------------------------------------------------------------
__device__ __align__(256) float g_V[9 * MH];
__device__ __align__(256) float g_P[3 * MH];
__device__ __align__(256) float g_dinv3[3 * M_NODES];
__device__ __align__(256) int   g_cnt[3 * M_NODES];
__device__ __align__(256) int   g_cur[3 * M_NODES];
__device__ __align__(256) int   g_blk[3 * SCAN_NBLK];
__device__ __align__(256) int   g_sorted[(size_t)3 * N_EDGES];

__device__ __align__(256) __nv_bfloat16 g_Bt1h[3 * 128 * 256];
__device__ __align__(256) __nv_bfloat16 g_Bt1l[3 * 128 * 256];
__device__ __align__(256) __nv_bfloat16 g_Bt2h[3 * 128 * 128];
__device__ __align__(256) __nv_bfloat16 g_Bt2l[3 * 128 * 128];
__device__ __align__(256) __nv_bfloat16 g_Bt3h[3 * 128 * 128];   // combos C0,C1,C2 [n][k]
__device__ __align__(256) __nv_bfloat16 g_Bt3l[3 * 128 * 128];

__device__ __forceinline__ float leaky(float v) { return v > 0.0f ? v : 0.01f * v; }

__device__ __forceinline__ uint32_t s2u(const void* p) {
    uint32_t a;
    asm("{ .reg .u64 t; cvta.to.shared.u64 t, %1; cvt.u32.u64 %0, t; }" : "=r"(a) : "l"(p));
    return a;
}
__device__ __forceinline__ void ldm_x4(uint32_t* r, uint32_t addr) {
    asm volatile("ldmatrix.sync.aligned.m8n8.x4.shared.b16 {%0,%1,%2,%3}, [%4];"
                 : "=r"(r[0]), "=r"(r[1]), "=r"(r[2]), "=r"(r[3]) : "r"(addr));
}
__device__ __forceinline__ void mma16816(float* c, const uint32_t* a, const uint32_t* b) {
    asm volatile(
        "mma.sync.aligned.m16n8k16.row.col.f32.bf16.bf16.f32 "
        "{%0,%1,%2,%3}, {%4,%5,%6,%7}, {%8,%9}, {%0,%1,%2,%3};"
        : "+f"(c[0]), "+f"(c[1]), "+f"(c[2]), "+f"(c[3])
        : "r"(a[0]), "r"(a[1]), "r"(a[2]), "r"(a[3]), "r"(b[0]), "r"(b[1]));
}
__device__ __forceinline__ void split2(float x, float y, uint32_t& hi, uint32_t& lo) {
    __nv_bfloat162 h;
    h.x = __float2bfloat16(x);
    h.y = __float2bfloat16(y);
    __nv_bfloat162 l;
    l.x = __float2bfloat16(x - __bfloat162float(h.x));
    l.y = __float2bfloat16(y - __bfloat162float(h.y));
    hi = *(uint32_t*)&h;
    lo = *(uint32_t*)&l;
}

#define SPAD 40
#define H1S  136

#define O_AH 0
#define O_AL (O_AH + 128 * SPAD)
#define O_BH (O_AL + 128 * SPAD)
#define O_BL (O_BH + 128 * SPAD)
#define O_H1H (O_BL + 128 * SPAD)
#define O_H1L (O_H1H + 128 * H1S)
#define SMEM_F12_BYTES ((O_H1L + 128 * H1S) * 2)

// ---------------------------------------------------------------------------
// Fused MLP + output projections (R15-exact synchronous version):
//   A: acc = x @ W1^T (K=256);  h1 = leaky(acc+b1) -> smem
//   C: acc = h1 @ W2^T (K=128); T0 = leaky(acc+b2) -> smem (overwrites h1)
//   Vj (j=0,1,2): g_V[rel][j] = T0 @ C_j^T (K=128, A from resident smem)
// ---------------------------------------------------------------------------
__global__ void __launch_bounds__(256, 1)
fused12v_kernel(const float* __restrict__ x,
                const float* __restrict__ b1_0, const float* __restrict__ b1_1,
                const float* __restrict__ b1_2,
                const float* __restrict__ b2_0, const float* __restrict__ b2_1,
                const float* __restrict__ b2_2) {
    extern __shared__ __nv_bfloat16 sm[];
    const int tid = threadIdx.x;
    const int wid = tid >> 5;
    const int lane = tid & 31;
    const int row0 = blockIdx.x * 128;
    const int rel = blockIdx.y;
    const int wm0 = (wid & 1) * 64;
    const int wn0 = (wid >> 1) * 32;

    const float* b1 = rel == 0 ? b1_0 : (rel == 1 ? b1_1 : b1_2);
    const float* b2 = rel == 0 ? b2_0 : (rel == 1 ? b2_1 : b2_2);

    const uint32_t base = s2u(sm);
    const uint32_t uAh = base + O_AH * 2, uAl = base + O_AL * 2;
    const uint32_t uBh = base + O_BH * 2, uBl = base + O_BL * 2;
    const uint32_t uH1h = base + O_H1H * 2, uH1l = base + O_H1L * 2;

    const int a_row = (lane & 7) + ((lane >> 3) & 1) * 8;
    const int a_kof = ((lane >> 4) & 1) * 8;
    const int b_nof = ((lane >> 4) & 1) * 8;
    const int b_kof = ((lane >> 3) & 1) * 8;
    const int b_row = lane & 7;
    const int lr = lane >> 2;
    const int lc = (lane & 3) * 2;

    float acc[4][4][4] = {};

    // ---------------- Phase A: x @ W1^T (K=256) ----------------
    const __nv_bfloat16* B1h = g_Bt1h + rel * 128 * 256;
    const __nv_bfloat16* B1l = g_Bt1l + rel * 128 * 256;
    for (int k0 = 0; k0 < 256; k0 += 32) {
        __syncthreads();
#pragma unroll
        for (int it = 0; it < 2; it++) {
            int i = it * 256 + tid;
            int r = i >> 2, q = (i & 3) * 8;
            int gr = row0 + r;
            float4 f0 = make_float4(0.f, 0.f, 0.f, 0.f);
            float4 f1 = make_float4(0.f, 0.f, 0.f, 0.f);
            if (gr < M_NODES) {
                const float* ap = x + (size_t)gr * 256 + k0 + q;
                f0 = *(const float4*)ap;
                f1 = *(const float4*)(ap + 4);
            }
            uint4 H, L;
            split2(f0.x, f0.y, H.x, L.x);
            split2(f0.z, f0.w, H.y, L.y);
            split2(f1.x, f1.y, H.z, L.z);
            split2(f1.z, f1.w, H.w, L.w);
            *(uint4*)(sm + O_AH + r * SPAD + q) = H;
            *(uint4*)(sm + O_AL + r * SPAD + q) = L;
            *(uint4*)(sm + O_BH + r * SPAD + q) = *(const uint4*)(B1h + (size_t)r * 256 + k0 + q);
            *(uint4*)(sm + O_BL + r * SPAD + q) = *(const uint4*)(B1l + (size_t)r * 256 + k0 + q);
        }
        __syncthreads();
#pragma unroll
        for (int ks = 0; ks < 32; ks += 16) {
            uint32_t ah[4][4], al[4][4], bh[4][2], bl[4][2];
#pragma unroll
            for (int mf = 0; mf < 4; mf++) {
                uint32_t off = ((wm0 + mf * 16 + a_row) * SPAD + ks + a_kof) * 2;
                ldm_x4(ah[mf], uAh + off);
                ldm_x4(al[mf], uAl + off);
            }
#pragma unroll
            for (int nb = 0; nb < 2; nb++) {
                uint32_t off = ((wn0 + nb * 16 + b_nof + b_row) * SPAD + ks + b_kof) * 2;
                uint32_t t[4];
                ldm_x4(t, uBh + off);
                bh[2 * nb][0] = t[0]; bh[2 * nb][1] = t[1];
                bh[2 * nb + 1][0] = t[2]; bh[2 * nb + 1][1] = t[3];
                ldm_x4(t, uBl + off);
                bl[2 * nb][0] = t[0]; bl[2 * nb][1] = t[1];
                bl[2 * nb + 1][0] = t[2]; bl[2 * nb + 1][1] = t[3];
            }
#pragma unroll
            for (int mf = 0; mf < 4; mf++)
#pragma unroll
                for (int nf = 0; nf < 4; nf++) {
                    mma16816(acc[mf][nf], ah[mf], bh[nf]);
                    mma16816(acc[mf][nf], ah[mf], bl[nf]);
                    mma16816(acc[mf][nf], al[mf], bh[nf]);
                }
        }
    }

    // h1 -> resident smem
    __syncthreads();
#pragma unroll
    for (int mf = 0; mf < 4; mf++)
#pragma unroll
        for (int half = 0; half < 2; half++) {
            int row = wm0 + mf * 16 + lr + half * 8;
#pragma unroll
            for (int nf = 0; nf < 4; nf++) {
                int col = wn0 + nf * 8 + lc;
                float v0 = leaky(acc[mf][nf][2 * half]     + __ldg(b1 + col));
                float v1 = leaky(acc[mf][nf][2 * half + 1] + __ldg(b1 + col + 1));
                uint32_t hi, lo;
                split2(v0, v1, hi, lo);
                *(uint32_t*)(sm + O_H1H + row * H1S + col) = hi;
                *(uint32_t*)(sm + O_H1L + row * H1S + col) = lo;
            }
        }
#pragma unroll
    for (int mf = 0; mf < 4; mf++)
#pragma unroll
        for (int nf = 0; nf < 4; nf++)
#pragma unroll
            for (int q = 0; q < 4; q++) acc[mf][nf][q] = 0.f;

    // ---------------- Phase C: h1 @ W2^T (K=128) ----------------
    const __nv_bfloat16* B2h = g_Bt2h + rel * 128 * 128;
    const __nv_bfloat16* B2l = g_Bt2l + rel * 128 * 128;
    for (int k0 = 0; k0 < 128; k0 += 32) {
        __syncthreads();
#pragma unroll
        for (int it = 0; it < 2; it++) {
            int i = it * 256 + tid;
            int r = i >> 2, q = (i & 3) * 8;
            *(uint4*)(sm + O_BH + r * SPAD + q) = *(const uint4*)(B2h + (size_t)r * 128 + k0 + q);
            *(uint4*)(sm + O_BL + r * SPAD + q) = *(const uint4*)(B2l + (size_t)r * 128 + k0 + q);
        }
        __syncthreads();
#pragma unroll
        for (int ks = 0; ks < 32; ks += 16) {
            uint32_t ah[4][4], al[4][4], bh[4][2], bl[4][2];
#pragma unroll
            for (int mf = 0; mf < 4; mf++) {
                uint32_t off = ((wm0 + mf * 16 + a_row) * H1S + k0 + ks + a_kof) * 2;
                ldm_x4(ah[mf], uH1h + off);
                ldm_x4(al[mf], uH1l + off);
            }
#pragma unroll
            for (int nb = 0; nb < 2; nb++) {
                uint32_t off = ((wn0 + nb * 16 + b_nof + b_row) * SPAD + ks + b_kof) * 2;
                uint32_t t[4];
                ldm_x4(t, uBh + off);
                bh[2 * nb][0] = t[0]; bh[2 * nb][1] = t[1];
                bh[2 * nb + 1][0] = t[2]; bh[2 * nb + 1][1] = t[3];
                ldm_x4(t, uBl + off);
                bl[2 * nb][0] = t[0]; bl[2 * nb][1] = t[1];
                bl[2 * nb + 1][0] = t[2]; bl[2 * nb + 1][1] = t[3];
            }
#pragma unroll
            for (int mf = 0; mf < 4; mf++)
#pragma unroll
                for (int nf = 0; nf < 4; nf++) {
                    mma16816(acc[mf][nf], ah[mf], bh[nf]);
                    mma16816(acc[mf][nf], ah[mf], bl[nf]);
                    mma16816(acc[mf][nf], al[mf], bh[nf]);
                }
        }
    }

    // T0 = leaky(acc+b2) -> resident smem (overwrite h1)
    __syncthreads();   // all phase-C reads of H1 done
#pragma unroll
    for (int mf = 0; mf < 4; mf++)
#pragma unroll
        for (int half = 0; half < 2; half++) {
            int row = wm0 + mf * 16 + lr + half * 8;
#pragma unroll
            for (int nf = 0; nf < 4; nf++) {
                int col = wn0 + nf * 8 + lc;
                float v0 = leaky(acc[mf][nf][2 * half]     + __ldg(b2 + col));
                float v1 = leaky(acc[mf][nf][2 * half + 1] + __ldg(b2 + col + 1));
                uint32_t hi, lo;
                split2(v0, v1, hi, lo);
                *(uint32_t*)(sm + O_H1H + row * H1S + col) = hi;
                *(uint32_t*)(sm + O_H1L + row * H1S + col) = lo;
            }
        }

    // ---------------- V phases: g_V[rel][j] = T0 @ C_j^T (K=128) -------------
#pragma unroll 1
    for (int j = 0; j < 3; j++) {
#pragma unroll
        for (int mf = 0; mf < 4; mf++)
#pragma unroll
            for (int nf = 0; nf < 4; nf++)
#pragma unroll
                for (int q = 0; q < 4; q++) acc[mf][nf][q] = 0.f;

        const __nv_bfloat16* Bjh = g_Bt3h + j * 128 * 128;
        const __nv_bfloat16* Bjl = g_Bt3l + j * 128 * 128;
        for (int k0 = 0; k0 < 128; k0 += 32) {
            __syncthreads();
#pragma unroll
            for (int it = 0; it < 2; it++) {
                int i = it * 256 + tid;
                int r = i >> 2, q = (i & 3) * 8;
                *(uint4*)(sm + O_BH + r * SPAD + q) = *(const uint4*)(Bjh + (size_t)r * 128 + k0 + q);
                *(uint4*)(sm + O_BL + r * SPAD + q) = *(const uint4*)(Bjl + (size_t)r * 128 + k0 + q);
            }
            __syncthreads();
#pragma unroll
            for (int ks = 0; ks < 32; ks += 16) {
                uint32_t ah[4][4], al[4][4], bh[4][2], bl[4][2];
#pragma unroll
                for (int mf = 0; mf < 4; mf++) {
                    uint32_t off = ((wm0 + mf * 16 + a_row) * H1S + k0 + ks + a_kof) * 2;
                    ldm_x4(ah[mf], uH1h + off);
                    ldm_x4(al[mf], uH1l + off);
                }
#pragma unroll
                for (int nb = 0; nb < 2; nb++) {
                    uint32_t off = ((wn0 + nb * 16 + b_nof + b_row) * SPAD + ks + b_kof) * 2;
                    uint32_t t[4];
                    ldm_x4(t, uBh + off);
                    bh[2 * nb][0] = t[0]; bh[2 * nb][1] = t[1];
                    bh[2 * nb + 1][0] = t[2]; bh[2 * nb + 1][1] = t[3];
                    ldm_x4(t, uBl + off);
                    bl[2 * nb][0] = t[0]; bl[2 * nb][1] = t[1];
                    bl[2 * nb + 1][0] = t[2]; bl[2 * nb + 1][1] = t[3];
                }
#pragma unroll
                for (int mf = 0; mf < 4; mf++)
#pragma unroll
                    for (int nf = 0; nf < 4; nf++) {
                        mma16816(acc[mf][nf], ah[mf], bh[nf]);
                        mma16816(acc[mf][nf], ah[mf], bl[nf]);
                        mma16816(acc[mf][nf], al[mf], bh[nf]);
                    }
            }
        }

        float* Vj = g_V + (size_t)(rel * 3 + j) * MH;
#pragma unroll
        for (int mf = 0; mf < 4; mf++)
#pragma unroll
            for (int half = 0; half < 2; half++) {
                int row = row0 + wm0 + mf * 16 + lr + half * 8;
                if (row >= M_NODES) continue;
#pragma unroll
                for (int nf = 0; nf < 4; nf++) {
                    int col = wn0 + nf * 8 + lc;
                    *(float2*)(Vj + (size_t)row * H_DIM + col) =
                        make_float2(acc[mf][nf][2 * half], acc[mf][nf][2 * half + 1]);
                }
            }
    }
}

// ---------------------------------------------------------------------------
// Weight prep: W1/W2 split; W3 -> combos C0=e0+e1+e2, C1=e1+2e2, C2=e2
// ---------------------------------------------------------------------------
#define W1_TOT (3 * 128 * 256)
#define W2_TOT (3 * 128 * 128)
#define W3_TOT (128 * 128)

__global__ void convW_all(const float* __restrict__ W1a, const float* __restrict__ W1b,
                          const float* __restrict__ W1c, const float* __restrict__ W2a,
                          const float* __restrict__ W2b, const float* __restrict__ W2c,
                          const float* __restrict__ W3) {
    int i = blockIdx.x * blockDim.x + threadIdx.x;
    if (i < W1_TOT) {
        int r = i / 32768, rem = i % 32768, n = rem >> 8, k = rem & 255;
        const float* W = r == 0 ? W1a : (r == 1 ? W1b : W1c);
        float v = W[k * H_DIM + n];
        __nv_bfloat16 h = __float2bfloat16(v);
        g_Bt1h[i] = h;
        g_Bt1l[i] = __float2bfloat16(v - __bfloat162float(h));
        return;
    }
    i -= W1_TOT;
    if (i < W2_TOT) {
        int r = i >> 14, rem = i & 16383, n = rem >> 7, k = rem & 127;
        const float* W = r == 0 ? W2a : (r == 1 ? W2b : W2c);
        float v = W[k * H_DIM + n];
        __nv_bfloat16 h = __float2bfloat16(v);
        g_Bt2h[i] = h;
        g_Bt2l[i] = __float2bfloat16(v - __bfloat162float(h));
        return;
    }
    i -= W2_TOT;
    if (i < W3_TOT) {
        int n = i >> 7, k = i & 127;
        float w0 = W3[(0 * 128 + k) * 128 + n];
        float w1 = W3[(1 * 128 + k) * 128 + n];
        float w2 = W3[(2 * 128 + k) * 128 + n];
        float e0 = 3.0f * w0;
        float e1 = -3.0f * w0 + 3.0f * w1;
        float e2 = 0.75f * w0 - 1.5f * w1 + 0.75f * w2;
        float c[3];
        c[0] = e0 + e1 + e2;
        c[1] = e1 + 2.0f * e2;
        c[2] = e2;
#pragma unroll
        for (int s = 0; s < 3; s++) {
            __nv_bfloat16 h = __float2bfloat16(c[s]);
            g_Bt3h[s * 128 * 128 + n * 128 + k] = h;
            g_Bt3l[s * 128 * 128 + n * 128 + k] = __float2bfloat16(c[s] - __bfloat162float(h));
        }
    }
}

// ---------------------------------------------------------------------------
// Graph preprocessing
// ---------------------------------------------------------------------------
__global__ void zero_cnt_kernel() {
    int i = blockIdx.x * blockDim.x + threadIdx.x;
    if (i < 3 * M_NODES) g_cnt[i] = 0;
}
__global__ void deg3_kernel(const int* __restrict__ d0, const int* __restrict__ d1,
                            const int* __restrict__ d2) {
    int t = blockIdx.x * blockDim.x + threadIdx.x;
    if (t >= 3 * N_EDGES) return;
    int r = t / N_EDGES, e = t - r * N_EDGES;
    const int* d = r == 0 ? d0 : (r == 1 ? d1 : d2);
    atomicAdd(&g_cnt[r * M_NODES + __ldg(d + e)], 1);
}

__global__ void scanA_kernel() {
    __shared__ int wsum[8];
    const int r = blockIdx.y, b = blockIdx.x;
    const int tid = threadIdx.x;
    const int base = b * SCAN_TILE + tid * 16;

    int s = 0;
#pragma unroll
    for (int k = 0; k < 16; k++) {
        int i = base + k;
        if (i < M_NODES) {
            int v = g_cnt[r * M_NODES + i];
            g_dinv3[r * M_NODES + i] = rsqrtf(fmaxf((float)v, 1.0f));
            s += v;
        }
    }
#pragma unroll
    for (int o = 16; o > 0; o >>= 1) s += __shfl_down_sync(0xFFFFFFFFu, s, o);
    if ((tid & 31) == 0) wsum[tid >> 5] = s;
    __syncthreads();
    if (tid == 0) {
        int t = 0;
#pragma unroll
        for (int w = 0; w < 8; w++) t += wsum[w];
        g_blk[r * SCAN_NBLK + b] = t;
    }
}

__global__ void scanB_kernel() {
    int r = threadIdx.x;
    if (r >= 3) return;
    int run = 0;
#pragma unroll
    for (int b = 0; b < SCAN_NBLK; b++) {
        int t = g_blk[r * SCAN_NBLK + b];
        g_blk[r * SCAN_NBLK + b] = run;
        run += t;
    }
}

__global__ void scanC_kernel() {
    __shared__ int warp_sums[8];
    const int r = blockIdx.y, b = blockIdx.x;
    const int tid = threadIdx.x;
    const int lane = tid & 31;
    const int wid = tid >> 5;
    const int base = b * SCAN_TILE + tid * 16;

    int v[16];
    int tsum = 0;
#pragma unroll
    for (int k = 0; k < 16; k++) {
        int i = base + k;
        v[k] = (i < M_NODES) ? g_cnt[r * M_NODES + i] : 0;
        tsum += v[k];
    }
    int x = tsum;
#pragma unroll
    for (int o = 1; o < 32; o <<= 1) {
        int y = __shfl_up_sync(0xFFFFFFFFu, x, o);
        if (lane >= o) x += y;
    }
    if (lane == 31) warp_sums[wid] = x;
    __syncthreads();
    if (wid == 0 && lane < 8) {
        int w = warp_sums[lane];
#pragma unroll
        for (int o = 1; o < 8; o <<= 1) {
            int y = __shfl_up_sync(0xFFu, w, o);
            if (lane >= o) w += y;
        }
        warp_sums[lane] = w;
    }
    __syncthreads();
    int woff = (wid > 0) ? warp_sums[wid - 1] : 0;
    int run = g_blk[r * SCAN_NBLK + b] + woff + x - tsum;
#pragma unroll
    for (int k = 0; k < 16; k++) {
        int i = base + k;
        if (i < M_NODES) g_cur[r * M_NODES + i] = run;
        run += v[k];
    }
}

__global__ void fill_kernel(const int* __restrict__ s0, const int* __restrict__ s1,
                            const int* __restrict__ s2, const int* __restrict__ d0,
                            const int* __restrict__ d1, const int* __restrict__ d2) {
    int t = blockIdx.x * blockDim.x + threadIdx.x;
    if (t >= 3 * N_EDGES) return;
    int r = t / N_EDGES, e = t - r * N_EDGES;
    const int* sp = r == 0 ? s0 : (r == 1 ? s1 : s2);
    const int* dp = r == 0 ? d0 : (r == 1 ? d1 : d2);
    int s = __ldg(sp + e);
    int d = __ldg(dp + e);
    int p = atomicAdd(&g_cur[r * M_NODES + d], 1);
    g_sorted[(size_t)r * N_EDGES + p] = s;
}

// ---------------------------------------------------------------------------
// Step 1: P_r[n] = V1_r[n] - dinv[n] * sum_seg dinv[src] * V2_r[src]
// one warp per (rel, node); 4-edge unrolled gather
// ---------------------------------------------------------------------------
__global__ void __launch_bounds__(256) prop1_kernel() {
    int t = blockIdx.x * blockDim.x + threadIdx.x;
    int w = t >> 5;
    if (w >= 3 * M_NODES) return;
    const int lane = t & 31;
    const int r = w / M_NODES, n = w - r * M_NODES;
    const int rn = r * M_NODES + n;
    const int end = __ldg(&g_cur[rn]);
    const int cnt = __ldg(&g_cnt[rn]);
    int j = end - cnt;
    const int* ss = g_sorted + (size_t)r * N_EDGES;
    const float* V2 = g_V + (size_t)(r * 3 + 2) * MH;
    const float* dv = g_dinv3 + r * M_NODES;

    float4 a0 = make_float4(0.f, 0.f, 0.f, 0.f);
    float4 a1 = make_float4(0.f, 0.f, 0.f, 0.f);
    for (; j + 4 <= end; j += 4) {
        int s0 = __ldg(ss + j);
        int s1 = __ldg(ss + j + 1);
        int s2 = __ldg(ss + j + 2);
        int s3 = __ldg(ss + j + 3);
        float e0 = __ldg(dv + s0);
        float e1 = __ldg(dv + s1);
        float e2 = __ldg(dv + s2);
        float e3 = __ldg(dv + s3);
        float4 v0 = *(const float4*)(V2 + (size_t)s0 * H_DIM + lane * 4);
        float4 v1 = *(const float4*)(V2 + (size_t)s1 * H_DIM + lane * 4);
        float4 v2 = *(const float4*)(V2 + (size_t)s2 * H_DIM + lane * 4);
        float4 v3 = *(const float4*)(V2 + (size_t)s3 * H_DIM + lane * 4);
        a0.x += v0.x * e0; a0.y += v0.y * e0; a0.z += v0.z * e0; a0.w += v0.w * e0;
        a1.x += v1.x * e1; a1.y += v1.y * e1; a1.z += v1.z * e1; a1.w += v1.w * e1;
        a0.x += v2.x * e2; a0.y += v2.y * e2; a0.z += v2.z * e2; a0.w += v2.w * e2;
        a1.x += v3.x * e3; a1.y += v3.y * e3; a1.z += v3.z * e3; a1.w += v3.w * e3;
    }
    for (; j < end; j++) {
        int s0 = __ldg(ss + j);
        float e0 = __ldg(dv + s0);
        float4 v0 = *(const float4*)(V2 + (size_t)s0 * H_DIM + lane * 4);
        a0.x += v0.x * e0; a0.y += v0.y * e0; a0.z += v0.z * e0; a0.w += v0.w * e0;
    }
    float dn = __ldg(dv + n);
    float4 b = *(const float4*)(g_V + (size_t)(r * 3 + 1) * MH + (size_t)n * H_DIM + lane * 4);
    float4 o;
    o.x = b.x - (a0.x + a1.x) * dn;
    o.y = b.y - (a0.y + a1.y) * dn;
    o.z = b.z - (a0.z + a1.z) * dn;
    o.w = b.w - (a0.w + a1.w) * dn;
    *(float4*)(g_P + (size_t)r * MH + (size_t)n * H_DIM + lane * 4) = o;
}

// ---------------------------------------------------------------------------
// Step 2: out[n] = leaky( b3 + sum_r [ V0_r[n] - dinv_r[n]*sum_seg dinv_r[s]*P_r[s] ] )
// one warp per node; 4-edge unrolled gather
// ---------------------------------------------------------------------------
__global__ void __launch_bounds__(256) prop2_kernel(const float* __restrict__ b3,
                                                    float* __restrict__ out) {
    int t = blockIdx.x * blockDim.x + threadIdx.x;
    int n = t >> 5;
    if (n >= M_NODES) return;
    const int lane = t & 31;

    float4 acc = *(const float4*)(b3 + lane * 4);

#pragma unroll 1
    for (int r = 0; r < 3; r++) {
        const int rn = r * M_NODES + n;
        const int end = __ldg(&g_cur[rn]);
        const int cnt = __ldg(&g_cnt[rn]);
        int j = end - cnt;
        const int* ss = g_sorted + (size_t)r * N_EDGES;
        const float* P = g_P + (size_t)r * MH;
        const float* dv = g_dinv3 + r * M_NODES;

        float4 a0 = make_float4(0.f, 0.f, 0.f, 0.f);
        float4 a1 = make_float4(0.f, 0.f, 0.f, 0.f);
        for (; j + 4 <= end; j += 4) {
            int s0 = __ldg(ss + j);
            int s1 = __ldg(ss + j + 1);
            int s2 = __ldg(ss + j + 2);
            int s3 = __ldg(ss + j + 3);
            float e0 = __ldg(dv + s0);
            float e1 = __ldg(dv + s1);
            float e2 = __ldg(dv + s2);
            float e3 = __ldg(dv + s3);
            float4 v0 = *(const float4*)(P + (size_t)s0 * H_DIM + lane * 4);
            float4 v1 = *(const float4*)(P + (size_t)s1 * H_DIM + lane * 4);
            float4 v2 = *(const float4*)(P + (size_t)s2 * H_DIM + lane * 4);
            float4 v3 = *(const float4*)(P + (size_t)s3 * H_DIM + lane * 4);
            a0.x += v0.x * e0; a0.y += v0.y * e0; a0.z += v0.z * e0; a0.w += v0.w * e0;
            a1.x += v1.x * e1; a1.y += v1.y * e1; a1.z += v1.z * e1; a1.w += v1.w * e1;
            a0.x += v2.x * e2; a0.y += v2.y * e2; a0.z += v2.z * e2; a0.w += v2.w * e2;
            a1.x += v3.x * e3; a1.y += v3.y * e3; a1.z += v3.z * e3; a1.w += v3.w * e3;
        }
        for (; j < end; j++) {
            int s0 = __ldg(ss + j);
            float e0 = __ldg(dv + s0);
            float4 v0 = *(const float4*)(P + (size_t)s0 * H_DIM + lane * 4);
            a0.x += v0.x * e0; a0.y += v0.y * e0; a0.z += v0.z * e0; a0.w += v0.w * e0;
        }
        float dn = __ldg(dv + n);
        float4 V0 = *(const float4*)(g_V + (size_t)(r * 3) * MH + (size_t)n * H_DIM + lane * 4);
        acc.x += V0.x - (a0.x + a1.x) * dn;
        acc.y += V0.y - (a0.y + a1.y) * dn;
        acc.z += V0.z - (a0.z + a1.z) * dn;
        acc.w += V0.w - (a0.w + a1.w) * dn;
    }

    float4 o;
    o.x = leaky(acc.x); o.y = leaky(acc.y); o.z = leaky(acc.z); o.w = leaky(acc.w);
    *(float4*)(out + (size_t)n * H_DIM + lane * 4) = o;
}

// ---------------------------------------------------------------------------
// Launch
// ---------------------------------------------------------------------------
extern "C" void kernel_launch(void* const* d_in, const int* in_sizes, int n_in,
                              void* d_out, int out_size) {
    const float* x = (const float*)d_in[0];
    const int *src[3], *dst[3];
    const float *W1[3], *b1[3], *W2[3], *b2[3];
    const float *W3, *b3;

    if (in_sizes[3] == N_EDGES) {
        for (int r = 0; r < 3; r++) {
            src[r] = (const int*)d_in[1 + 2 * r];
            dst[r] = (const int*)d_in[2 + 2 * r];
        }
        for (int r = 0; r < 3; r++) {
            W1[r] = (const float*)d_in[7 + 4 * r];
            b1[r] = (const float*)d_in[8 + 4 * r];
            W2[r] = (const float*)d_in[9 + 4 * r];
            b2[r] = (const float*)d_in[10 + 4 * r];
        }
        W3 = (const float*)d_in[19];
        b3 = (const float*)d_in[20];
    } else {
        for (int r = 0; r < 3; r++) {
            src[r] = (const int*)d_in[1 + 6 * r];
            dst[r] = (const int*)d_in[2 + 6 * r];
            W1[r]  = (const float*)d_in[3 + 6 * r];
            b1[r]  = (const float*)d_in[4 + 6 * r];
            W2[r]  = (const float*)d_in[5 + 6 * r];
            b2[r]  = (const float*)d_in[6 + 6 * r];
        }
        W3 = (const float*)d_in[19];
        b3 = (const float*)d_in[20];
    }

    cudaFuncSetAttribute(fused12v_kernel, cudaFuncAttributeMaxDynamicSharedMemorySize,
                         SMEM_F12_BYTES);

    const int GEMM_X = (M_NODES + 127) / 128;                    // 391
    const int E3     = (3 * N_EDGES + 255) / 256;
    const int NV3    = (3 * M_NODES + 255) / 256;
    const int SEG3   = (int)(((size_t)3 * M_NODES * 32 + 255) / 256);
    const int SEG1   = (int)(((size_t)M_NODES * 32 + 255) / 256);
    const int CW     = (W1_TOT + W2_TOT + W3_TOT + 255) / 256;

    cudaStream_t sSide;
    cudaEvent_t evFork, evPrep;
    cudaStreamCreateWithFlags(&sSide, cudaStreamNonBlocking);
    cudaEventCreateWithFlags(&evFork, cudaEventDisableTiming);
    cudaEventCreateWithFlags(&evPrep, cudaEventDisableTiming);

    cudaEventRecord(evFork, 0);
    cudaStreamWaitEvent(sSide, evFork, 0);

    // Side chain: graph preprocessing (overlaps the GEMM work)
    zero_cnt_kernel<<<NV3, 256, 0, sSide>>>();
    deg3_kernel<<<E3, 256, 0, sSide>>>(dst[0], dst[1], dst[2]);
    {
        dim3 sg(SCAN_NBLK, 3);
        scanA_kernel<<<sg, 256, 0, sSide>>>();
        scanB_kernel<<<1, 32, 0, sSide>>>();
        scanC_kernel<<<sg, 256, 0, sSide>>>();
    }
    fill_kernel<<<E3, 256, 0, sSide>>>(src[0], src[1], src[2], dst[0], dst[1], dst[2]);
    cudaEventRecord(evPrep, sSide);

    // Main: all GEMM work (MLP + output projections V0/V1/V2)
    convW_all<<<CW, 256>>>(W1[0], W1[1], W1[2], W2[0], W2[1], W2[2], W3);
    {
        dim3 g(GEMM_X, 3);
        fused12v_kernel<<<g, 256, SMEM_F12_BYTES>>>(x, b1[0], b1[1], b1[2], b2[0], b2[1], b2[2]);
    }

    // Propagation directly produces the output
    cudaStreamWaitEvent(0, evPrep, 0);
    prop1_kernel<<<SEG3, 256>>>();
    prop2_kernel<<<SEG1, 256>>>(b3, (float*)d_out);
}